// round 1
// baseline (speedup 1.0000x reference)
#include <cuda_runtime.h>
#include <math.h>

typedef unsigned long long ull;

#define PNUM 2548      // number of masked positions (exact)
#define PPAD 2560      // padded N for GEMM
#define QMAX 16384
#define CIN  768
#define MROWS 6912     // 768 cout * 9 offsets

// ---------------- scratch (static device globals; no allocation) -------------
__device__ float d_V[CIN * PPAD];        // B matrix [cin][p]
__device__ float d_Wt[MROWS * CIN];      // A matrix [(cout*9+o)][cin]
__device__ float d_Y[MROWS * PPAD];      // GEMM out
__device__ float d_H[CIN * QMAX];        // conv1 out at dilated cells
__device__ int   d_pidx[QMAX];
__device__ int   d_qmap[QMAX];
__device__ int   d_src[9 * QMAX];
__device__ int   d_qcount;
__device__ int   d_qofp[PNUM];
__device__ int   d_ppi[PNUM];
__device__ int   d_ppj[PNUM];
__device__ float d_chsum[CIN];
__device__ float d_chsq[CIN];
__device__ float d_mu[4];
__device__ float d_rs[4];
__device__ float d_scores[PNUM];

// ---------------- packed fp32x2 helpers (sm_103a) -----------------------------
__device__ __forceinline__ ull pack2(float lo, float hi) {
    ull r; asm("mov.b64 %0, {%1, %2};" : "=l"(r) : "f"(lo), "f"(hi)); return r;
}
__device__ __forceinline__ void ffma2(ull& d, ull a, ull b) {
    asm("fma.rn.f32x2 %0, %1, %2, %0;" : "+l"(d) : "l"(a), "l"(b));
}

// ---------------- K0: build static structure ----------------------------------
__global__ void k_build() {
    const int tid = threadIdx.x; // 1024
    __shared__ unsigned char flg[16384];
    __shared__ int psum[1024];

    for (int i = tid; i < QMAX; i += 1024) d_pidx[i] = -1;
    __syncthreads();

    if (tid < 128) { d_ppi[tid] = tid; d_ppj[tid] = tid; d_pidx[tid * 128 + tid] = tid; }
    {
        int len = 128, pbase = 128, stride = 1, offset = 0;
        const int counts[4] = {15, 8, 8, 8};
        for (int g = 0; g < 4; ++g) {
            for (int t = 0; t < counts[g]; ++t) {
                offset += stride;
                bool k3 = (g > 0 && t == 0);
                int nl = k3 ? (len - 1) / 2 : (len - 1);
                for (int u = tid; u < nl; u += 1024) {
                    int ii = u * stride, jj = offset + u * stride, p = pbase + u;
                    d_ppi[p] = ii; d_ppj[p] = jj; d_pidx[ii * 128 + jj] = p;
                }
                pbase += nl; len = nl;
            }
            stride <<= 1;
        }
    }
    __syncthreads();

    // flags: dilated mask
    int cnt = 0;
    for (int s = 0; s < 16; ++s) {
        int cell = tid * 16 + s;
        int qi = cell >> 7, qj = cell & 127;
        bool f = false;
        #pragma unroll
        for (int o = 0; o < 9; ++o) {
            int ni = qi + o / 3 - 1, nj = qj + o % 3 - 1;
            if (ni >= 0 && ni < 128 && nj >= 0 && nj < 128 && d_pidx[ni * 128 + nj] >= 0) f = true;
        }
        flg[cell] = f ? 1 : 0; cnt += f ? 1 : 0;
    }
    psum[tid] = cnt; __syncthreads();
    for (int off = 1; off < 1024; off <<= 1) {
        int v = (tid >= off) ? psum[tid - off] : 0;
        __syncthreads();
        psum[tid] += v;
        __syncthreads();
    }
    int run = psum[tid] - cnt;
    for (int s = 0; s < 16; ++s) {
        int cell = tid * 16 + s;
        if (flg[cell]) {
            int q = run++;
            int qi = cell >> 7, qj = cell & 127;
            #pragma unroll
            for (int o = 0; o < 9; ++o) {
                int ni = qi + o / 3 - 1, nj = qj + o % 3 - 1;
                int v = (ni >= 0 && ni < 128 && nj >= 0 && nj < 128) ? d_pidx[ni * 128 + nj] : -1;
                d_src[o * QMAX + q] = v;
            }
            d_qmap[cell] = q;
        } else d_qmap[cell] = -1;
    }
    __syncthreads();
    if (tid == 0) d_qcount = psum[1023];
    for (int p = tid; p < PNUM; p += 1024) d_qofp[p] = d_qmap[d_ppi[p] * 128 + d_ppj[p]];
}

// ---------------- K1: sparse max pool (values into V) --------------------------
__global__ void k_pool(const float* __restrict__ fea) {
    const int c = blockIdx.x;       // 768
    const int tid = threadIdx.x;    // 128
    __shared__ float x[128];
    x[tid] = fea[c * 128 + tid];
    d_V[c * PPAD + tid] = x[tid];   // diagonal positions p = tid
    __syncthreads();
    int len = 128, pbase = 128, stride = 1, offset = 0;
    const int counts[4] = {15, 8, 8, 8};
    for (int g = 0; g < 4; ++g) {
        for (int t = 0; t < counts[g]; ++t) {
            offset += stride;
            bool k3 = (g > 0 && t == 0);
            int nl = k3 ? (len - 1) / 2 : (len - 1);
            float v = 0.f;
            if (tid < nl)
                v = k3 ? fmaxf(fmaxf(x[2 * tid], x[2 * tid + 1]), x[2 * tid + 2])
                       : fmaxf(x[tid], x[tid + 1]);
            __syncthreads();
            if (tid < nl) { x[tid] = v; d_V[c * PPAD + pbase + tid] = v; }
            __syncthreads();
            pbase += nl; len = nl;
        }
        stride <<= 1;
    }
}

// ---------------- K2: weight transpose W[cout][cin][3][3] -> Wt ---------------
__global__ void k_wt(const float* __restrict__ w) {
    int idx = blockIdx.x * 256 + threadIdx.x;
    if (idx >= MROWS * CIN) return;
    int m = idx / CIN, k = idx % CIN;
    int cout = m / 9, o = m % 9;
    d_Wt[idx] = w[(cout * CIN + k) * 9 + o];
}

// ---------------- K3: SGEMM 6912 x 2560 x 768, fp32x2 packed FMA --------------
__global__ __launch_bounds__(256, 2) void k_gemm() {
    __shared__ float As[2][16][128];
    __shared__ float Bs[2][16][128];
    const int tid = threadIdx.x;
    const int bn0 = blockIdx.x * 128;
    const int bm0 = blockIdx.y * 128;
    const int tx = tid & 15, ty = tid >> 4;
    const int arow = tid >> 2;
    const int acol4 = (tid & 3) * 4;
    const int brow = tid >> 5;
    const int bcol = (tid & 31) * 4;

    const float* Ag = d_Wt + bm0 * CIN;
    const float* Bg = d_V + bn0;

    ull acc[8][4];
    #pragma unroll
    for (int i = 0; i < 8; i++)
        #pragma unroll
        for (int j = 0; j < 4; j++) acc[i][j] = 0ull;

    // prologue: tile 0
    {
        float4 a0 = *(const float4*)(Ag + arow * CIN + acol4);
        float4 a1 = *(const float4*)(Ag + (arow + 64) * CIN + acol4);
        float4 b0 = *(const float4*)(Bg + brow * PPAD + bcol);
        float4 b1 = *(const float4*)(Bg + (brow + 8) * PPAD + bcol);
        As[0][acol4 + 0][arow] = a0.x; As[0][acol4 + 1][arow] = a0.y;
        As[0][acol4 + 2][arow] = a0.z; As[0][acol4 + 3][arow] = a0.w;
        As[0][acol4 + 0][arow + 64] = a1.x; As[0][acol4 + 1][arow + 64] = a1.y;
        As[0][acol4 + 2][arow + 64] = a1.z; As[0][acol4 + 3][arow + 64] = a1.w;
        *(float4*)(&Bs[0][brow][bcol]) = b0;
        *(float4*)(&Bs[0][brow + 8][bcol]) = b1;
    }
    __syncthreads();

    int cur = 0;
    for (int kt = 0; kt < 48; ++kt) {
        float4 na0, na1, nb0, nb1;
        if (kt < 47) {
            const float* Ak = Ag + (kt + 1) * 16;
            na0 = *(const float4*)(Ak + arow * CIN + acol4);
            na1 = *(const float4*)(Ak + (arow + 64) * CIN + acol4);
            const float* Bk = Bg + (kt + 1) * 16 * PPAD;
            nb0 = *(const float4*)(Bk + brow * PPAD + bcol);
            nb1 = *(const float4*)(Bk + (brow + 8) * PPAD + bcol);
        }
        #pragma unroll
        for (int kk = 0; kk < 16; ++kk) {
            float a8[8];
            *(float4*)(a8)     = *(const float4*)(&As[cur][kk][ty * 8]);
            *(float4*)(a8 + 4) = *(const float4*)(&As[cur][kk][ty * 8 + 4]);
            ull bb[4];
            const ull* bp = (const ull*)(&Bs[cur][kk][tx * 8]);
            bb[0] = bp[0]; bb[1] = bp[1]; bb[2] = bp[2]; bb[3] = bp[3];
            #pragma unroll
            for (int i = 0; i < 8; i++) {
                ull aa = pack2(a8[i], a8[i]);
                ffma2(acc[i][0], aa, bb[0]);
                ffma2(acc[i][1], aa, bb[1]);
                ffma2(acc[i][2], aa, bb[2]);
                ffma2(acc[i][3], aa, bb[3]);
            }
        }
        if (kt < 47) {
            int nxt = cur ^ 1;
            As[nxt][acol4 + 0][arow] = na0.x; As[nxt][acol4 + 1][arow] = na0.y;
            As[nxt][acol4 + 2][arow] = na0.z; As[nxt][acol4 + 3][arow] = na0.w;
            As[nxt][acol4 + 0][arow + 64] = na1.x; As[nxt][acol4 + 1][arow + 64] = na1.y;
            As[nxt][acol4 + 2][arow + 64] = na1.z; As[nxt][acol4 + 3][arow + 64] = na1.w;
            *(float4*)(&Bs[nxt][brow][bcol]) = nb0;
            *(float4*)(&Bs[nxt][brow + 8][bcol]) = nb1;
            __syncthreads();
            cur = nxt;
        }
    }
    float* Cp = d_Y + (bm0 + ty * 8) * (size_t)PPAD + bn0 + tx * 8;
    #pragma unroll
    for (int i = 0; i < 8; i++)
        #pragma unroll
        for (int j = 0; j < 4; j++)
            *(ull*)(Cp + (size_t)i * PPAD + j * 2) = acc[i][j];
}

// ---------------- K4: scatter Y -> H -------------------------------------------
__global__ void k_scatter() {
    int q = blockIdx.x * 128 + threadIdx.x;
    int c = blockIdx.y;
    if (q >= d_qcount) return;
    float s = 0.f;
    #pragma unroll
    for (int o = 0; o < 9; ++o) {
        int p = d_src[o * QMAX + q];
        if (p >= 0) s += d_Y[(size_t)(c * 9 + o) * PPAD + p];
    }
    d_H[(size_t)c * QMAX + q] = s;
}

// ---------------- K5: per-channel sums -----------------------------------------
__global__ void k_stats() {
    const int c = blockIdx.x;
    const int tid = threadIdx.x; // 256
    __shared__ float ss[256], sq[256];
    int qc = d_qcount;
    float s = 0.f, q2 = 0.f;
    const float* row = d_H + (size_t)c * QMAX;
    for (int i = tid; i < qc; i += 256) { float v = row[i]; s += v; q2 += v * v; }
    ss[tid] = s; sq[tid] = q2; __syncthreads();
    for (int st = 128; st > 0; st >>= 1) {
        if (tid < st) { ss[tid] += ss[tid + st]; sq[tid] += sq[tid + st]; }
        __syncthreads();
    }
    if (tid == 0) { d_chsum[c] = ss[0]; d_chsq[c] = sq[0]; }
}

// ---------------- K6: group stats ----------------------------------------------
__global__ void k_grp() {
    const int tid = threadIdx.x; // 256
    int c0 = tid * 3;
    float s = d_chsum[c0] + d_chsum[c0 + 1] + d_chsum[c0 + 2];
    float q = d_chsq[c0] + d_chsq[c0 + 1] + d_chsq[c0 + 2];
    for (int off = 16; off > 0; off >>= 1) {
        s += __shfl_down_sync(0xffffffff, s, off);
        q += __shfl_down_sync(0xffffffff, q, off);
    }
    __shared__ float ws[8], wq[8];
    int warp = tid >> 5;
    if ((tid & 31) == 0) { ws[warp] = s; wq[warp] = q; }
    __syncthreads();
    if (tid < 4) {
        float S = ws[tid * 2] + ws[tid * 2 + 1];
        float Q = wq[tid * 2] + wq[tid * 2 + 1];
        float inv = 1.0f / (192.0f * 16384.0f);
        float mu = S * inv;
        float var = Q * inv - mu * mu;
        d_mu[tid] = mu;
        d_rs[tid] = 1.0f / sqrtf(var + 1e-5f);
    }
}

// ---------------- K7: scores at masked positions -------------------------------
__global__ void k_scores(const float* __restrict__ gamma, const float* __restrict__ beta,
                         const float* __restrict__ w2) {
    const int p = blockIdx.x;    // PNUM
    const int tid = threadIdx.x; // 128
    __shared__ float red[128];
    int q = d_qofp[p];
    float acc = 0.f;
    for (int c = tid; c < CIN; c += 128) {
        float x = d_H[(size_t)c * QMAX + q];
        int g = c / 192;
        float v = (x - d_mu[g]) * d_rs[g] * gamma[c] + beta[c];
        v = fmaxf(v, 0.f);
        acc += v * w2[c];
    }
    red[tid] = acc; __syncthreads();
    for (int st = 64; st > 0; st >>= 1) {
        if (tid < st) red[tid] += red[tid + st];
        __syncthreads();
    }
    if (tid == 0) d_scores[p] = red[0]; // monotonic in sigmoid(out+b2): skip both
}

// ---------------- K8: sort + greedy NMS + output --------------------------------
__device__ __forceinline__ float read_duration(const void* p) {
    unsigned u = *(const unsigned*)p;
    float f = __int_as_float(u);
    if (f > 1e-3f && f < 1e7f) return f;
    int i = (int)u;
    if (i > 0 && i < 10000000) return (float)i;
    double d = *(const double*)p;
    if (d > 1e-3 && d < 1e7) return (float)d;
    return 30.0f;
}

__global__ void k_nms(const void* __restrict__ dur_ptr, float* __restrict__ out) {
    const int tid = threadIdx.x; // 1024
    __shared__ float skey[4096];
    __shared__ int   sidx[4096];
    __shared__ unsigned char sup[PNUM];
    __shared__ int s_next;

    float dur = read_duration(dur_ptr);
    float scale = dur / 128.0f;

    for (int i = tid; i < 4096; i += 1024) {
        if (i < PNUM) { skey[i] = d_scores[i]; sidx[i] = i; }
        else          { skey[i] = -INFINITY;  sidx[i] = 0; }
    }
    for (int i = tid; i < PNUM; i += 1024) sup[i] = 0;
    __syncthreads();

    // bitonic sort, descending by score
    for (int k = 2; k <= 4096; k <<= 1) {
        for (int j = k >> 1; j > 0; j >>= 1) {
            for (int i = tid; i < 4096; i += 1024) {
                int ixj = i ^ j;
                if (ixj > i) {
                    bool up = ((i & k) == 0);
                    float a = skey[i], b = skey[ixj];
                    bool sw = up ? (a < b) : (a > b);
                    if (sw) {
                        skey[i] = b; skey[ixj] = a;
                        int t = sidx[i]; sidx[i] = sidx[ixj]; sidx[ixj] = t;
                    }
                }
            }
            __syncthreads();
        }
    }

    // sorted moments (reuse the two arrays)
    for (int i = tid; i < PNUM; i += 1024) {
        int p = sidx[i];
        float st = d_ppi[p] * scale;
        float en = (d_ppj[p] + 1) * scale;
        skey[i] = st;
        ((float*)sidx)[i] = en;
    }
    __syncthreads();
    float* sst = skey;
    float* sen = (float*)sidx;

    int cnt = 0, cur = 0;
    while (cnt < 5 && cur < PNUM) {
        if (tid == 0) s_next = PNUM;
        __syncthreads();
        int cand = cur + tid;
        if (cand < PNUM && !sup[cand]) atomicMin(&s_next, cand);
        __syncthreads();
        int i = s_next;
        if (i >= PNUM) { cur += 1024; __syncthreads(); continue; }
        float si = sst[i], ei = sen[i];
        if (tid == 0) { out[cnt * 2] = si; out[cnt * 2 + 1] = ei; }
        for (int j = i + 1 + tid; j < PNUM; j += 1024) {
            if (!sup[j]) {
                float inter = fminf(sen[j], ei) - fmaxf(sst[j], si);
                inter = fmaxf(inter, 0.f);
                float uni = fmaxf(sen[j], ei) - fminf(sst[j], si);
                if (inter / uni > 0.5f) sup[j] = 1;
            }
        }
        cnt++; cur = i + 1;
        __syncthreads();
    }
    // fallback: fewer than 5 keepers -> suppressed in ascending sorted index (matches top_k of pri)
    if (tid == 0 && cnt < 5) {
        for (int i = 0; i < PNUM && cnt < 5; ++i)
            if (sup[i]) { out[cnt * 2] = sst[i]; out[cnt * 2 + 1] = sen[i]; cnt++; }
    }
}

// ---------------- launch ---------------------------------------------------------
extern "C" void kernel_launch(void* const* d_in, const int* in_sizes, int n_in,
                              void* d_out, int out_size) {
    const float* fea     = (const float*)d_in[0];
    const void*  durp    = d_in[1];
    const float* conv1_w = (const float*)d_in[2];
    const float* gamma   = (const float*)d_in[3];
    const float* beta    = (const float*)d_in[4];
    const float* conv2_w = (const float*)d_in[5];
    float* out = (float*)d_out;

    k_build<<<1, 1024>>>();
    k_pool<<<768, 128>>>(fea);
    k_wt<<<(MROWS * CIN + 255) / 256, 256>>>(conv1_w);
    k_gemm<<<dim3(PPAD / 128, MROWS / 128), 256>>>();
    k_scatter<<<dim3(QMAX / 128, CIN), 128>>>();
    k_stats<<<CIN, 256>>>();
    k_grp<<<1, 256>>>();
    k_scores<<<PNUM, 128>>>(gamma, beta, conv2_w);
    k_nms<<<1, 1024>>>(durp, out);
}

// round 3
// speedup vs baseline: 1.6386x; 1.6386x over previous
#include <cuda_runtime.h>
#include <cuda_bf16.h>
#include <math.h>

typedef unsigned long long ull;

#define PNUM 2548      // number of masked positions (exact)
#define PPAD 2560      // padded N for GEMM
#define QMAX 16384
#define CIN  768
#define MROWS 6912     // 768 cout * 9 offsets
#define KK   2304      // 3 * 768 (hi*hi, hi*lo, lo*hi segments)
#define NCH  72        // K chunks of 32

// ---------------- scratch (static device globals; no allocation) -------------
__device__ float d_V[CIN * PPAD];
__device__ __align__(128) __nv_bfloat16 d_A2[(size_t)MROWS * KK];
__device__ __align__(128) __nv_bfloat16 d_B2[(size_t)PPAD * KK];
__device__ float d_Y[(size_t)MROWS * PPAD];
__device__ float d_H[(size_t)CIN * QMAX];
__device__ int   d_pidx[QMAX];
__device__ int   d_qmap[QMAX];
__device__ int   d_src[9 * QMAX];
__device__ int   d_qcount;
__device__ int   d_qofp[PNUM];
__device__ int   d_ppi[PNUM];
__device__ int   d_ppj[PNUM];
__device__ float d_chsum[CIN];
__device__ float d_chsq[CIN];
__device__ float d_mu[4];
__device__ float d_rs[4];
__device__ float d_scores[PNUM];

// ---------------- helpers ------------------------------------------------------
__device__ __forceinline__ unsigned smem_u32(const void* p) {
    unsigned a;
    asm("{ .reg .u64 t; cvta.to.shared.u64 t, %1; cvt.u32.u64 %0, t; }" : "=r"(a) : "l"(p));
    return a;
}
__device__ __forceinline__ void cp16(unsigned dst, const void* src) {
    asm volatile("cp.async.cg.shared.global [%0], [%1], 16;" :: "r"(dst), "l"(src) : "memory");
}
__device__ __forceinline__ void cp_commit() {
    asm volatile("cp.async.commit_group;" ::: "memory");
}
__device__ __forceinline__ void cp_wait1() {
    asm volatile("cp.async.wait_group 1;" ::: "memory");
}
__device__ __forceinline__ void cp_wait0() {
    asm volatile("cp.async.wait_group 0;" ::: "memory");
}
__device__ __forceinline__ void ldmx4(unsigned addr, unsigned& r0, unsigned& r1, unsigned& r2, unsigned& r3) {
    asm volatile("ldmatrix.sync.aligned.m8n8.x4.shared.b16 {%0,%1,%2,%3}, [%4];"
                 : "=r"(r0), "=r"(r1), "=r"(r2), "=r"(r3) : "r"(addr));
}
__device__ __forceinline__ void mma16816(float* c, const unsigned* a, const unsigned* b) {
    asm volatile(
        "mma.sync.aligned.m16n8k16.row.col.f32.bf16.bf16.f32 "
        "{%0,%1,%2,%3},{%4,%5,%6,%7},{%8,%9},{%0,%1,%2,%3};"
        : "+f"(c[0]), "+f"(c[1]), "+f"(c[2]), "+f"(c[3])
        : "r"(a[0]), "r"(a[1]), "r"(a[2]), "r"(a[3]), "r"(b[0]), "r"(b[1]));
}
__device__ __forceinline__ unsigned pkbf2(float a, float b) {
    __nv_bfloat16 x = __float2bfloat16_rn(a), y = __float2bfloat16_rn(b);
    unsigned short ux = *(unsigned short*)&x, uy = *(unsigned short*)&y;
    return (unsigned)ux | ((unsigned)uy << 16);
}

// ---------------- K0: build static structure ----------------------------------
__global__ void k_build() {
    const int tid = threadIdx.x; // 1024
    __shared__ unsigned char flg[16384];
    __shared__ int psum[1024];

    for (int i = tid; i < QMAX; i += 1024) d_pidx[i] = -1;
    __syncthreads();

    if (tid < 128) { d_ppi[tid] = tid; d_ppj[tid] = tid; d_pidx[tid * 128 + tid] = tid; }
    {
        int len = 128, pbase = 128, stride = 1, offset = 0;
        const int counts[4] = {15, 8, 8, 8};
        for (int g = 0; g < 4; ++g) {
            for (int t = 0; t < counts[g]; ++t) {
                offset += stride;
                bool k3 = (g > 0 && t == 0);
                int nl = k3 ? (len - 1) / 2 : (len - 1);
                for (int u = tid; u < nl; u += 1024) {
                    int ii = u * stride, jj = offset + u * stride, p = pbase + u;
                    d_ppi[p] = ii; d_ppj[p] = jj; d_pidx[ii * 128 + jj] = p;
                }
                pbase += nl; len = nl;
            }
            stride <<= 1;
        }
    }
    __syncthreads();

    int cnt = 0;
    for (int s = 0; s < 16; ++s) {
        int cell = tid * 16 + s;
        int qi = cell >> 7, qj = cell & 127;
        bool f = false;
        #pragma unroll
        for (int o = 0; o < 9; ++o) {
            int ni = qi + o / 3 - 1, nj = qj + o % 3 - 1;
            if (ni >= 0 && ni < 128 && nj >= 0 && nj < 128 && d_pidx[ni * 128 + nj] >= 0) f = true;
        }
        flg[cell] = f ? 1 : 0; cnt += f ? 1 : 0;
    }
    psum[tid] = cnt; __syncthreads();
    for (int off = 1; off < 1024; off <<= 1) {
        int v = (tid >= off) ? psum[tid - off] : 0;
        __syncthreads();
        psum[tid] += v;
        __syncthreads();
    }
    int run = psum[tid] - cnt;
    for (int s = 0; s < 16; ++s) {
        int cell = tid * 16 + s;
        if (flg[cell]) {
            int q = run++;
            int qi = cell >> 7, qj = cell & 127;
            #pragma unroll
            for (int o = 0; o < 9; ++o) {
                int ni = qi + o / 3 - 1, nj = qj + o % 3 - 1;
                int v = (ni >= 0 && ni < 128 && nj >= 0 && nj < 128) ? d_pidx[ni * 128 + nj] : -1;
                d_src[o * QMAX + q] = v;
            }
            d_qmap[cell] = q;
        } else d_qmap[cell] = -1;
    }
    __syncthreads();
    if (tid == 0) d_qcount = psum[1023];
    for (int p = tid; p < PNUM; p += 1024) d_qofp[p] = d_qmap[d_ppi[p] * 128 + d_ppj[p]];
}

// ---------------- K1: sparse max pool ------------------------------------------
__global__ void k_pool(const float* __restrict__ fea) {
    const int c = blockIdx.x;
    const int tid = threadIdx.x;
    __shared__ float x[128];
    x[tid] = fea[c * 128 + tid];
    d_V[c * PPAD + tid] = x[tid];
    __syncthreads();
    int len = 128, pbase = 128, stride = 1, offset = 0;
    const int counts[4] = {15, 8, 8, 8};
    for (int g = 0; g < 4; ++g) {
        for (int t = 0; t < counts[g]; ++t) {
            offset += stride;
            bool k3 = (g > 0 && t == 0);
            int nl = k3 ? (len - 1) / 2 : (len - 1);
            float v = 0.f;
            if (tid < nl)
                v = k3 ? fmaxf(fmaxf(x[2 * tid], x[2 * tid + 1]), x[2 * tid + 2])
                       : fmaxf(x[tid], x[tid + 1]);
            __syncthreads();
            if (tid < nl) { x[tid] = v; d_V[c * PPAD + pbase + tid] = v; }
            __syncthreads();
            pbase += nl; len = nl;
        }
        stride <<= 1;
    }
}

// ---------------- K2a: build A' (bf16 hi/lo split) ------------------------------
__global__ void k_asplit(const float* __restrict__ w) {
    const int cout = blockIdx.x;
    const int tid = threadIdx.x;
    __shared__ float ws[CIN * 9];
    for (int i = tid; i < CIN * 9; i += 256) ws[i] = w[(size_t)cout * CIN * 9 + i];
    __syncthreads();
    #pragma unroll
    for (int o = 0; o < 9; ++o) {
        size_t mrow = (size_t)(cout * 9 + o) * KK;
        for (int k2 = tid; k2 < 384; k2 += 256) {
            int k = k2 * 2;
            float x0 = ws[k * 9 + o], x1 = ws[(k + 1) * 9 + o];
            float h0f = __bfloat162float(__float2bfloat16_rn(x0));
            float h1f = __bfloat162float(__float2bfloat16_rn(x1));
            unsigned hi = pkbf2(x0, x1);
            unsigned lo = pkbf2(x0 - h0f, x1 - h1f);
            *(unsigned*)&d_A2[mrow + k]        = hi;
            *(unsigned*)&d_A2[mrow + 768 + k]  = hi;
            *(unsigned*)&d_A2[mrow + 1536 + k] = lo;
        }
    }
}

// ---------------- K2b: build B' (transpose + split) ----------------------------
__global__ void k_bsplit() {
    __shared__ float tile[32][33];
    const int tx = threadIdx.x, ty = threadIdx.y;
    const int p0 = blockIdx.x * 32, c0 = blockIdx.y * 32;
    #pragma unroll
    for (int i = ty; i < 32; i += 8)
        tile[i][tx] = (p0 + tx < PNUM) ? d_V[(size_t)(c0 + i) * PPAD + p0 + tx] : 0.f;
    __syncthreads();
    #pragma unroll
    for (int i = ty; i < 32; i += 8) {
        if (tx < 16) {
            int p = p0 + i;
            int k = c0 + tx * 2;
            float x0 = tile[tx * 2][i], x1 = tile[tx * 2 + 1][i];
            float h0f = __bfloat162float(__float2bfloat16_rn(x0));
            float h1f = __bfloat162float(__float2bfloat16_rn(x1));
            unsigned hi = pkbf2(x0, x1);
            unsigned lo = pkbf2(x0 - h0f, x1 - h1f);
            size_t prow = (size_t)p * KK;
            *(unsigned*)&d_B2[prow + k]        = hi;
            *(unsigned*)&d_B2[prow + 768 + k]  = lo;
            *(unsigned*)&d_B2[prow + 1536 + k] = hi;
        }
    }
}

// ---------------- K3: bf16 mma.sync GEMM 6912 x 2560 x 2304 --------------------
// CTA 128x128, 8 warps (2m x 4n), warp 64x32, K-chunks of 32, 3-stage cp.async.
__global__ void __launch_bounds__(256, 2) k_gemm_mma() {
    __shared__ __align__(16) uint4 smbuf[3][1024];  // per stage: A 512 uint4, B 512 uint4
    const int tid = threadIdx.x;
    const int wid = tid >> 5;
    const int lane = tid & 31;
    const int wm = wid >> 2;         // 0..1
    const int wn = wid & 3;          // 0..3
    const int bn0 = blockIdx.x * 128;
    const int bm0 = blockIdx.y * 128;

    const unsigned smb = smem_u32(&smbuf[0][0]);

    const __nv_bfloat16* Ag = d_A2 + (size_t)bm0 * KK;
    const __nv_bfloat16* Bg = d_B2 + (size_t)bn0 * KK;

    // cp.async: 4 chunks of 16B per thread per stage (A:512, B:512)
    auto issue = [&](int kc, int buf) {
        unsigned base = smb + buf * 16384;
        #pragma unroll
        for (int j = 0; j < 4; ++j) {
            int cid = tid + j * 256;          // 0..1023
            int half = cid >> 9;              // 0:A 1:B
            int lc = cid & 511;
            int r = lc >> 2, c = lc & 3;
            unsigned dst = base + half * 8192 + (unsigned)(r * 64 + ((c ^ ((r >> 1) & 3)) << 4));
            const __nv_bfloat16* src = (half ? Bg : Ag) + (size_t)r * KK + kc * 32 + c * 8;
            cp16(dst, src);
        }
        cp_commit();
    };

    float acc[4][4][4];
    #pragma unroll
    for (int i = 0; i < 4; i++)
        #pragma unroll
        for (int j = 0; j < 4; j++)
            #pragma unroll
            for (int v = 0; v < 4; v++) acc[i][j][v] = 0.f;

    issue(0, 0);
    issue(1, 1);

    // precompute ldmatrix lane addressing
    const int l15 = lane & 15, hl = lane >> 4;
    const int rowA = wm * 64 + l15;
    const int sA = (rowA >> 1) & 3;
    const int rowB0 = wn * 32 + l15;        // nt2 = 0
    const int rowB1 = rowB0 + 16;           // nt2 = 1
    const int sB0 = (rowB0 >> 1) & 3;
    const int sB1 = (rowB1 >> 1) & 3;

    for (int kt = 0; kt < NCH; ++kt) {
        if (kt < NCH - 1) cp_wait1(); else cp_wait0();
        __syncthreads();
        if (kt + 2 < NCH) issue(kt + 2, (kt + 2) % 3);

        unsigned Asm = smb + (kt % 3) * 16384;
        unsigned Bsm = Asm + 8192;

        #pragma unroll
        for (int kg = 0; kg < 2; ++kg) {
            unsigned af[4][4], bf[4][2];
            #pragma unroll
            for (int mt = 0; mt < 4; ++mt) {
                unsigned addr = Asm + (unsigned)((rowA + mt * 16) * 64 + (((kg * 2 + hl) ^ sA) << 4));
                ldmx4(addr, af[mt][0], af[mt][1], af[mt][2], af[mt][3]);
            }
            {
                unsigned addr0 = Bsm + (unsigned)(rowB0 * 64 + (((kg * 2 + hl) ^ sB0) << 4));
                unsigned r0, r1, r2, r3;
                ldmx4(addr0, r0, r1, r2, r3);
                bf[0][0] = r0; bf[1][0] = r1; bf[0][1] = r2; bf[1][1] = r3;
                unsigned addr1 = Bsm + (unsigned)(rowB1 * 64 + (((kg * 2 + hl) ^ sB1) << 4));
                ldmx4(addr1, r0, r1, r2, r3);
                bf[2][0] = r0; bf[3][0] = r1; bf[2][1] = r2; bf[3][1] = r3;
            }
            #pragma unroll
            for (int mt = 0; mt < 4; ++mt)
                #pragma unroll
                for (int nt = 0; nt < 4; ++nt)
                    mma16816(acc[mt][nt], af[mt], bf[nt]);
        }
        __syncthreads();
    }

    // epilogue: direct global stores
    const int r0 = lane >> 2, c0 = (lane & 3) * 2;
    #pragma unroll
    for (int mt = 0; mt < 4; ++mt) {
        int m = bm0 + wm * 64 + mt * 16 + r0;
        float* y0 = d_Y + (size_t)m * PPAD + bn0 + wn * 32;
        float* y1 = y0 + 8 * PPAD;
        #pragma unroll
        for (int nt = 0; nt < 4; ++nt) {
            *(float2*)(y0 + nt * 8 + c0) = make_float2(acc[mt][nt][0], acc[mt][nt][1]);
            *(float2*)(y1 + nt * 8 + c0) = make_float2(acc[mt][nt][2], acc[mt][nt][3]);
        }
    }
}

// ---------------- K4: scatter Y -> H -------------------------------------------
__global__ void k_scatter() {
    int q = blockIdx.x * 128 + threadIdx.x;
    int c = blockIdx.y;
    if (q >= d_qcount) return;
    float s = 0.f;
    #pragma unroll
    for (int o = 0; o < 9; ++o) {
        int p = d_src[o * QMAX + q];
        if (p >= 0) s += d_Y[(size_t)(c * 9 + o) * PPAD + p];
    }
    d_H[(size_t)c * QMAX + q] = s;
}

// ---------------- K5: per-channel sums -----------------------------------------
__global__ void k_stats() {
    const int c = blockIdx.x;
    const int tid = threadIdx.x;
    __shared__ float ss[256], sq[256];
    int qc = d_qcount;
    float s = 0.f, q2 = 0.f;
    const float* row = d_H + (size_t)c * QMAX;
    for (int i = tid; i < qc; i += 256) { float v = row[i]; s += v; q2 += v * v; }
    ss[tid] = s; sq[tid] = q2; __syncthreads();
    for (int st = 128; st > 0; st >>= 1) {
        if (tid < st) { ss[tid] += ss[tid + st]; sq[tid] += sq[tid + st]; }
        __syncthreads();
    }
    if (tid == 0) { d_chsum[c] = ss[0]; d_chsq[c] = sq[0]; }
}

// ---------------- K6: group stats ----------------------------------------------
__global__ void k_grp() {
    const int tid = threadIdx.x;
    int c0 = tid * 3;
    float s = d_chsum[c0] + d_chsum[c0 + 1] + d_chsum[c0 + 2];
    float q = d_chsq[c0] + d_chsq[c0 + 1] + d_chsq[c0 + 2];
    for (int off = 16; off > 0; off >>= 1) {
        s += __shfl_down_sync(0xffffffff, s, off);
        q += __shfl_down_sync(0xffffffff, q, off);
    }
    __shared__ float ws[8], wq[8];
    int warp = tid >> 5;
    if ((tid & 31) == 0) { ws[warp] = s; wq[warp] = q; }
    __syncthreads();
    if (tid < 4) {
        float S = ws[tid * 2] + ws[tid * 2 + 1];
        float Q = wq[tid * 2] + wq[tid * 2 + 1];
        float inv = 1.0f / (192.0f * 16384.0f);
        float mu = S * inv;
        float var = Q * inv - mu * mu;
        d_mu[tid] = mu;
        d_rs[tid] = 1.0f / sqrtf(var + 1e-5f);
    }
}

// ---------------- K7: scores at masked positions -------------------------------
__global__ void k_scores(const float* __restrict__ gamma, const float* __restrict__ beta,
                         const float* __restrict__ w2) {
    const int p = blockIdx.x;
    const int tid = threadIdx.x;
    __shared__ float red[128];
    int q = d_qofp[p];
    float acc = 0.f;
    for (int c = tid; c < CIN; c += 128) {
        float x = d_H[(size_t)c * QMAX + q];
        int g = c / 192;
        float v = (x - d_mu[g]) * d_rs[g] * gamma[c] + beta[c];
        v = fmaxf(v, 0.f);
        acc += v * w2[c];
    }
    red[tid] = acc; __syncthreads();
    for (int st = 64; st > 0; st >>= 1) {
        if (tid < st) red[tid] += red[tid + st];
        __syncthreads();
    }
    if (tid == 0) d_scores[p] = red[0];
}

// ---------------- K8: sort + greedy NMS + output --------------------------------
__device__ __forceinline__ float read_duration(const void* p) {
    unsigned u = *(const unsigned*)p;
    float f = __int_as_float(u);
    if (f > 1e-3f && f < 1e7f) return f;
    int i = (int)u;
    if (i > 0 && i < 10000000) return (float)i;
    double d = *(const double*)p;
    if (d > 1e-3 && d < 1e7) return (float)d;
    return 30.0f;
}

__global__ void k_nms(const void* __restrict__ dur_ptr, float* __restrict__ out) {
    const int tid = threadIdx.x;
    __shared__ float skey[4096];
    __shared__ int   sidx[4096];
    __shared__ unsigned char sup[PNUM];
    __shared__ int s_next;

    float dur = read_duration(dur_ptr);
    float scale = dur / 128.0f;

    for (int i = tid; i < 4096; i += 1024) {
        if (i < PNUM) { skey[i] = d_scores[i]; sidx[i] = i; }
        else          { skey[i] = -INFINITY;  sidx[i] = 0; }
    }
    for (int i = tid; i < PNUM; i += 1024) sup[i] = 0;
    __syncthreads();

    for (int k = 2; k <= 4096; k <<= 1) {
        for (int j = k >> 1; j > 0; j >>= 1) {
            for (int i = tid; i < 4096; i += 1024) {
                int ixj = i ^ j;
                if (ixj > i) {
                    bool up = ((i & k) == 0);
                    float a = skey[i], b = skey[ixj];
                    bool sw = up ? (a < b) : (a > b);
                    if (sw) {
                        skey[i] = b; skey[ixj] = a;
                        int t = sidx[i]; sidx[i] = sidx[ixj]; sidx[ixj] = t;
                    }
                }
            }
            __syncthreads();
        }
    }

    for (int i = tid; i < PNUM; i += 1024) {
        int p = sidx[i];
        float st = d_ppi[p] * scale;
        float en = (d_ppj[p] + 1) * scale;
        skey[i] = st;
        ((float*)sidx)[i] = en;
    }
    __syncthreads();
    float* sst = skey;
    float* sen = (float*)sidx;

    int cnt = 0, cur = 0;
    while (cnt < 5 && cur < PNUM) {
        if (tid == 0) s_next = PNUM;
        __syncthreads();
        int cand = cur + tid;
        if (cand < PNUM && !sup[cand]) atomicMin(&s_next, cand);
        __syncthreads();
        int i = s_next;
        if (i >= PNUM) { cur += 1024; __syncthreads(); continue; }
        float si = sst[i], ei = sen[i];
        if (tid == 0) { out[cnt * 2] = si; out[cnt * 2 + 1] = ei; }
        for (int j = i + 1 + tid; j < PNUM; j += 1024) {
            if (!sup[j]) {
                float inter = fminf(sen[j], ei) - fmaxf(sst[j], si);
                inter = fmaxf(inter, 0.f);
                float uni = fmaxf(sen[j], ei) - fminf(sst[j], si);
                if (inter / uni > 0.5f) sup[j] = 1;
            }
        }
        cnt++; cur = i + 1;
        __syncthreads();
    }
    if (tid == 0 && cnt < 5) {
        for (int i = 0; i < PNUM && cnt < 5; ++i)
            if (sup[i]) { out[cnt * 2] = sst[i]; out[cnt * 2 + 1] = sen[i]; cnt++; }
    }
}

// ---------------- launch ---------------------------------------------------------
extern "C" void kernel_launch(void* const* d_in, const int* in_sizes, int n_in,
                              void* d_out, int out_size) {
    const float* fea     = (const float*)d_in[0];
    const void*  durp    = d_in[1];
    const float* conv1_w = (const float*)d_in[2];
    const float* gamma   = (const float*)d_in[3];
    const float* beta    = (const float*)d_in[4];
    const float* conv2_w = (const float*)d_in[5];
    float* out = (float*)d_out;

    k_build<<<1, 1024>>>();
    k_pool<<<768, 128>>>(fea);
    k_asplit<<<768, 256>>>(conv1_w);
    k_bsplit<<<dim3(PPAD / 32, CIN / 32), dim3(32, 8)>>>();
    k_gemm_mma<<<dim3(PPAD / 128, MROWS / 128), 256>>>();
    k_scatter<<<dim3(QMAX / 128, CIN), 128>>>();
    k_stats<<<CIN, 256>>>();
    k_grp<<<1, 256>>>();
    k_scores<<<PNUM, 128>>>(gamma, beta, conv2_w);
    k_nms<<<1, 1024>>>(durp, out);
}